// round 16
// baseline (speedup 1.0000x reference)
#include <cuda_runtime.h>
#include <cuda_bf16.h>
#include <cstdint>

#define RT_TOT 65536
#define BR     128
#define NTHR   256
#define NGRID  (RT_TOT / BR)   // 512 CTAs

// fragment tables: uint4 = {hi_b0, hi_b1, lo_b0, lo_b1}
__device__ uint4 g_simB4[8192];  // [kc16][nt16][lane32]  (8KB per kc chunk)
__device__ uint4 g_zB4[8192];    // [dc4][kz8][nt8][lane32] (4KB per (dc,kz) chunk)

__device__ __forceinline__ void split2(float a, float b, uint32_t& hi, uint32_t& lo) {
    uint32_t h2;
    asm("cvt.rn.bf16x2.f32 %0, %1, %2;" : "=r"(h2) : "f"(b), "f"(a));
    float ha = __uint_as_float(h2 << 16);
    float hb = __uint_as_float(h2 & 0xffff0000u);
    float la = a - ha, lb = b - hb;
    uint32_t l2;
    asm("cvt.rn.bf16x2.f32 %0, %1, %2;" : "=r"(l2) : "f"(lb), "f"(la));
    hi = h2; lo = l2;
}

__global__ void prep_kernel(const float* __restrict__ proto) {
    int id = blockIdx.x * blockDim.x + threadIdx.x;   // 16384 threads
    if (id < 8192) {
        // sim B: k = d (contraction), n = codebook c
        int lane = id & 31, nt = (id >> 5) & 15, kc = (id >> 9) & 15;
        int d0 = kc * 16 + (lane & 3) * 2;
        int c  = nt * 8 + (lane >> 2);
        uint32_t h0, l0, h1, l1;
        split2(proto[c * 256 + d0],     proto[c * 256 + d0 + 1], h0, l0);
        split2(proto[c * 256 + d0 + 8], proto[c * 256 + d0 + 9], h1, l1);
        g_simB4[id] = make_uint4(h0, h1, l0, l1);
    } else {
        // z B: k = codebook c (contraction), n = d; chunked by (dc, kz)
        int e = id - 8192;
        int lane = e & 31, nt = (e >> 5) & 7, kz = (e >> 8) & 7, dc = (e >> 11) & 3;
        int d  = dc * 64 + nt * 8 + (lane >> 2);
        int c0 = kz * 16 + (lane & 3) * 2;
        uint32_t h0, l0, h1, l1;
        split2(proto[c0 * 256 + d],       proto[(c0 + 1) * 256 + d], h0, l0);
        split2(proto[(c0 + 8) * 256 + d], proto[(c0 + 9) * 256 + d], h1, l1);
        g_zB4[e] = make_uint4(h0, h1, l0, l1);
    }
}

#define MMA4(c, a0, a1, a2, a3, b0, b1)                                     \
    asm volatile("mma.sync.aligned.m16n8k16.row.col.f32.bf16.bf16.f32 "     \
        "{%0,%1,%2,%3}, {%4,%5,%6,%7}, {%8,%9}, {%0,%1,%2,%3};"             \
        : "+f"((c)[0]), "+f"((c)[1]), "+f"((c)[2]), "+f"((c)[3])            \
        : "r"(a0), "r"(a1), "r"(a2), "r"(a3), "r"(b0), "r"(b1))

__device__ __forceinline__ uint32_t smem_u32(const void* p) {
    uint32_t a;
    asm("{ .reg .u64 t; cvta.to.shared.u64 t, %1; cvt.u32.u64 %0, t; }" : "=r"(a) : "l"(p));
    return a;
}
__device__ __forceinline__ void cp16(uint32_t dst, const void* src) {
    asm volatile("cp.async.cg.shared.global [%0], [%1], 16;" :: "r"(dst), "l"(src) : "memory");
}
#define CP_COMMIT() asm volatile("cp.async.commit_group;" ::: "memory")
#define CP_WAIT(n)  asm volatile("cp.async.wait_group %0;" :: "n"(n) : "memory")

__global__ __launch_bounds__(NTHR, 2) void softcodebook_mma_kernel(
    const float* __restrict__ h, float* __restrict__ out)
{
    __shared__ uint4 sbuf[2048];   // 32KB ring (sim: 4x8KB, z: 8x4KB)
    const uint32_t sb = smem_u32(sbuf);
    const int tid = threadIdx.x;
    const int w = tid >> 5, lid = tid & 31;     // 8 warps
    const int g = lid >> 2, t4 = lid & 3;
    const int row0 = blockIdx.x * BR;

    // ---- prologue: async-stage sim chunks 0,1 ----
    cp16(sb + (uint32_t)(0 * 512 + tid) * 16, g_simB4 + 0 * 512 + tid);
    cp16(sb + (uint32_t)(0 * 512 + tid + 256) * 16, g_simB4 + 0 * 512 + tid + 256);
    CP_COMMIT();
    cp16(sb + (uint32_t)(1 * 512 + tid) * 16, g_simB4 + 1 * 512 + tid);
    cp16(sb + (uint32_t)(1 * 512 + tid + 256) * 16, g_simB4 + 1 * 512 + tid + 256);
    CP_COMMIT();

    // ---- warp-private row norms (batched 4 rows for MLP) ----
    float myrinv = 0.0f;
    #pragma unroll 1
    for (int b = 0; b < 4; ++b) {
        float4 va[4], vb[4];
        #pragma unroll
        for (int j = 0; j < 4; ++j) {
            const float4* hp = (const float4*)(h + (size_t)(row0 + w * 16 + b * 4 + j) * 256);
            va[j] = hp[lid]; vb[j] = hp[lid + 32];
        }
        #pragma unroll
        for (int j = 0; j < 4; ++j) {
            float ss = va[j].x*va[j].x + va[j].y*va[j].y + va[j].z*va[j].z + va[j].w*va[j].w
                     + vb[j].x*vb[j].x + vb[j].y*vb[j].y + vb[j].z*vb[j].z + vb[j].w*vb[j].w;
            #pragma unroll
            for (int o = 16; o >= 1; o >>= 1) ss += __shfl_xor_sync(0xffffffffu, ss, o);
            if (lid == b * 4 + j) myrinv = 1.0f / fmaxf(sqrtf(ss), 1e-12f);
        }
    }
    const float s0r = __shfl_sync(0xffffffffu, myrinv, g);
    const float s1r = __shfl_sync(0xffffffffu, myrinv, g + 8);

    // sim accumulators: C[nt][4] -> rows (g, g+8), cols nt*8 + t4*2 (+1)
    float C[16][4];
    #pragma unroll
    for (int nt = 0; nt < 16; ++nt)
        #pragma unroll
        for (int j = 0; j < 4; ++j) C[nt][j] = 0.0f;

    // ---- sim GEMM: 16 k-chunks, B streamed, 4-way interleaved MMA chains ----
    const size_t rA = (size_t)(row0 + w * 16 + g) * 256;
    const size_t rB = rA + 8 * 256;
    float2 v0, v1, v2, v3;
    {
        int db = t4 * 2;
        v0 = *(const float2*)(h + rA + db);
        v1 = *(const float2*)(h + rB + db);
        v2 = *(const float2*)(h + rA + db + 8);
        v3 = *(const float2*)(h + rB + db + 8);
    }
    #pragma unroll 1
    for (int kc = 0; kc < 16; ++kc) {
        if (kc + 2 < 16) {
            int c = kc + 2, bi = c & 3;
            cp16(sb + (uint32_t)(bi * 512 + tid) * 16, g_simB4 + c * 512 + tid);
            cp16(sb + (uint32_t)(bi * 512 + tid + 256) * 16, g_simB4 + c * 512 + tid + 256);
            CP_COMMIT();
            CP_WAIT(2);
        } else if (kc + 1 < 16) {
            CP_WAIT(1);
        } else {
            CP_WAIT(0);
        }
        __syncthreads();

        float2 n0, n1, n2, n3;
        if (kc < 15) {
            int db = (kc + 1) * 16 + t4 * 2;
            n0 = *(const float2*)(h + rA + db);
            n1 = *(const float2*)(h + rB + db);
            n2 = *(const float2*)(h + rA + db + 8);
            n3 = *(const float2*)(h + rB + db + 8);
        }
        uint32_t a0, a1, a2, a3, l0, l1, l2, l3;
        split2(v0.x * s0r, v0.y * s0r, a0, l0);
        split2(v1.x * s1r, v1.y * s1r, a1, l1);
        split2(v2.x * s0r, v2.y * s0r, a2, l2);
        split2(v3.x * s1r, v3.y * s1r, a3, l3);
        const uint4* Bp = sbuf + (kc & 3) * 512 + lid;
        #pragma unroll
        for (int q = 0; q < 4; ++q) {
            uint4 b0 = Bp[(q * 4 + 0) * 32];
            uint4 b1 = Bp[(q * 4 + 1) * 32];
            uint4 b2 = Bp[(q * 4 + 2) * 32];
            uint4 b3 = Bp[(q * 4 + 3) * 32];
            // pass-major over 4 independent accumulators: no same-C adjacency
            MMA4(C[q*4+0], a0, a1, a2, a3, b0.x, b0.y);
            MMA4(C[q*4+1], a0, a1, a2, a3, b1.x, b1.y);
            MMA4(C[q*4+2], a0, a1, a2, a3, b2.x, b2.y);
            MMA4(C[q*4+3], a0, a1, a2, a3, b3.x, b3.y);
            MMA4(C[q*4+0], l0, l1, l2, l3, b0.x, b0.y);
            MMA4(C[q*4+1], l0, l1, l2, l3, b1.x, b1.y);
            MMA4(C[q*4+2], l0, l1, l2, l3, b2.x, b2.y);
            MMA4(C[q*4+3], l0, l1, l2, l3, b3.x, b3.y);
            MMA4(C[q*4+0], a0, a1, a2, a3, b0.z, b0.w);
            MMA4(C[q*4+1], a0, a1, a2, a3, b1.z, b1.w);
            MMA4(C[q*4+2], a0, a1, a2, a3, b2.z, b2.w);
            MMA4(C[q*4+3], a0, a1, a2, a3, b3.z, b3.w);
        }
        v0 = n0; v1 = n1; v2 = n2; v3 = n3;
    }

    // ---- softmax over K=128 (quad shfl), write p, split to PH/PL regs ----
    uint32_t PH[8][4], PL[8][4];
    {
        float mx0 = -1e30f, mx1 = -1e30f;
        #pragma unroll
        for (int nt = 0; nt < 16; ++nt) {
            mx0 = fmaxf(mx0, fmaxf(C[nt][0], C[nt][1]));
            mx1 = fmaxf(mx1, fmaxf(C[nt][2], C[nt][3]));
        }
        mx0 = fmaxf(mx0, __shfl_xor_sync(0xffffffffu, mx0, 1));
        mx0 = fmaxf(mx0, __shfl_xor_sync(0xffffffffu, mx0, 2));
        mx1 = fmaxf(mx1, __shfl_xor_sync(0xffffffffu, mx1, 1));
        mx1 = fmaxf(mx1, __shfl_xor_sync(0xffffffffu, mx1, 2));
        float s0 = 0.0f, s1 = 0.0f;
        #pragma unroll
        for (int nt = 0; nt < 16; ++nt) {
            C[nt][0] = __expf((C[nt][0] - mx0) * 10.0f); s0 += C[nt][0];
            C[nt][1] = __expf((C[nt][1] - mx0) * 10.0f); s0 += C[nt][1];
            C[nt][2] = __expf((C[nt][2] - mx1) * 10.0f); s1 += C[nt][2];
            C[nt][3] = __expf((C[nt][3] - mx1) * 10.0f); s1 += C[nt][3];
        }
        s0 += __shfl_xor_sync(0xffffffffu, s0, 1);
        s0 += __shfl_xor_sync(0xffffffffu, s0, 2);
        s1 += __shfl_xor_sync(0xffffffffu, s1, 1);
        s1 += __shfl_xor_sync(0xffffffffu, s1, 2);
        float i0 = 1.0f / s0, i1 = 1.0f / s1;
        size_t prow0 = (size_t)(row0 + w * 16 + g) * 128 + t4 * 2;
        size_t prow1 = prow0 + 8 * 128;
        #pragma unroll
        for (int nt = 0; nt < 16; ++nt) {
            C[nt][0] *= i0; C[nt][1] *= i0;
            C[nt][2] *= i1; C[nt][3] *= i1;
            *(float2*)(out + prow0 + nt * 8) = make_float2(C[nt][0], C[nt][1]);
            *(float2*)(out + prow1 + nt * 8) = make_float2(C[nt][2], C[nt][3]);
        }
        #pragma unroll
        for (int kz = 0; kz < 8; ++kz) {
            split2(C[2 * kz][0],     C[2 * kz][1],     PH[kz][0], PL[kz][0]);
            split2(C[2 * kz][2],     C[2 * kz][3],     PH[kz][1], PL[kz][1]);
            split2(C[2 * kz + 1][0], C[2 * kz + 1][1], PH[kz][2], PL[kz][2]);
            split2(C[2 * kz + 1][2], C[2 * kz + 1][3], PH[kz][3], PL[kz][3]);
        }
    }

    // ---- z prologue: stage z chunks 0..3 (4KB each, ring of 8) ----
    #pragma unroll
    for (int zc = 0; zc < 4; ++zc) {
        cp16(sb + (uint32_t)(zc * 256 + tid) * 16, g_zB4 + zc * 256 + tid);
        CP_COMMIT();
    }

    // ---- z GEMM: A = p (PH/PL regs), B streamed, 4-way interleaved chains ----
    float* zout = out + (size_t)RT_TOT * 128;
    #pragma unroll 1
    for (int dc = 0; dc < 4; ++dc) {
        float Z[8][4];
        #pragma unroll
        for (int nt = 0; nt < 8; ++nt)
            #pragma unroll
            for (int j = 0; j < 4; ++j) Z[nt][j] = 0.0f;

        #pragma unroll 1
        for (int kz = 0; kz < 8; ++kz) {
            int zc = dc * 8 + kz;
            if (zc + 4 < 32) {
                int c = zc + 4;
                cp16(sb + (uint32_t)((c & 7) * 256 + tid) * 16, g_zB4 + c * 256 + tid);
                CP_COMMIT();
                CP_WAIT(4);
            } else {
                int rem = 31 - zc;
                if (rem == 3)      { CP_WAIT(3); }
                else if (rem == 2) { CP_WAIT(2); }
                else if (rem == 1) { CP_WAIT(1); }
                else               { CP_WAIT(0); }
            }
            __syncthreads();

            const uint4* Bp = sbuf + (zc & 7) * 256 + lid;
            #pragma unroll
            for (int q = 0; q < 2; ++q) {
                uint4 b0 = Bp[(q * 4 + 0) * 32];
                uint4 b1 = Bp[(q * 4 + 1) * 32];
                uint4 b2 = Bp[(q * 4 + 2) * 32];
                uint4 b3 = Bp[(q * 4 + 3) * 32];
                MMA4(Z[q*4+0], PH[kz][0], PH[kz][1], PH[kz][2], PH[kz][3], b0.x, b0.y);
                MMA4(Z[q*4+1], PH[kz][0], PH[kz][1], PH[kz][2], PH[kz][3], b1.x, b1.y);
                MMA4(Z[q*4+2], PH[kz][0], PH[kz][1], PH[kz][2], PH[kz][3], b2.x, b2.y);
                MMA4(Z[q*4+3], PH[kz][0], PH[kz][1], PH[kz][2], PH[kz][3], b3.x, b3.y);
                MMA4(Z[q*4+0], PL[kz][0], PL[kz][1], PL[kz][2], PL[kz][3], b0.x, b0.y);
                MMA4(Z[q*4+1], PL[kz][0], PL[kz][1], PL[kz][2], PL[kz][3], b1.x, b1.y);
                MMA4(Z[q*4+2], PL[kz][0], PL[kz][1], PL[kz][2], PL[kz][3], b2.x, b2.y);
                MMA4(Z[q*4+3], PL[kz][0], PL[kz][1], PL[kz][2], PL[kz][3], b3.x, b3.y);
                MMA4(Z[q*4+0], PH[kz][0], PH[kz][1], PH[kz][2], PH[kz][3], b0.z, b0.w);
                MMA4(Z[q*4+1], PH[kz][0], PH[kz][1], PH[kz][2], PH[kz][3], b1.z, b1.w);
                MMA4(Z[q*4+2], PH[kz][0], PH[kz][1], PH[kz][2], PH[kz][3], b2.z, b2.w);
                MMA4(Z[q*4+3], PH[kz][0], PH[kz][1], PH[kz][2], PH[kz][3], b3.z, b3.w);
            }
        }
        {
            size_t zr0 = (size_t)(row0 + w * 16 + g) * 256 + dc * 64 + t4 * 2;
            size_t zr1 = zr0 + 8 * 256;
            #pragma unroll
            for (int nt = 0; nt < 8; ++nt) {
                *(float2*)(zout + zr0 + nt * 8) = make_float2(Z[nt][0], Z[nt][1]);
                *(float2*)(zout + zr1 + nt * 8) = make_float2(Z[nt][2], Z[nt][3]);
            }
        }
    }
}

extern "C" void kernel_launch(void* const* d_in, const int* in_sizes, int n_in,
                              void* d_out, int out_size) {
    const float* h     = (const float*)d_in[0];   // (64,1024,256) fp32
    const float* proto = (const float*)d_in[1];   // (128,256) fp32
    float* out = (float*)d_out;                   // p (65536*128) ++ z (65536*256)

    prep_kernel<<<64, 256>>>(proto);
    softcodebook_mma_kernel<<<NGRID, NTHR>>>(h, out);
}

// round 17
// speedup vs baseline: 1.2828x; 1.2828x over previous
#include <cuda_runtime.h>
#include <cuda_fp16.h>
#include <cstdint>

#define RT_TOT 65536
#define BR     128
#define NTHR   256
#define NGRID  (RT_TOT / BR)   // 512 CTAs

// fp16 hi-only fragment tables
__device__ uint2 g_simB2[8192];  // [kc16][nt16][lane32]  (4KB per kc chunk)
__device__ uint2 g_zB2[8192];    // [dc4][kz8][nt8][lane32] (2KB per (dc,kz) chunk)

__device__ __forceinline__ uint32_t packh(float a, float b) {
    __half2 t = __floats2half2_rn(a, b);
    return *(uint32_t*)&t;
}
__device__ __forceinline__ void split2h(float a, float b, uint32_t& hi, uint32_t& lo) {
    __half2 hh = __floats2half2_rn(a, b);
    float ha = __half2float(__low2half(hh));
    float hb = __half2float(__high2half(hh));
    __half2 ll = __floats2half2_rn(a - ha, b - hb);
    hi = *(uint32_t*)&hh;
    lo = *(uint32_t*)&ll;
}

__global__ void prep_kernel(const float* __restrict__ proto) {
    int id = blockIdx.x * blockDim.x + threadIdx.x;   // 16384 threads
    if (id < 8192) {
        // sim B: k = d (contraction), n = codebook c
        int lane = id & 31, nt = (id >> 5) & 15, kc = (id >> 9) & 15;
        int d0 = kc * 16 + (lane & 3) * 2;
        int c  = nt * 8 + (lane >> 2);
        uint32_t h0 = packh(proto[c * 256 + d0],     proto[c * 256 + d0 + 1]);
        uint32_t h1 = packh(proto[c * 256 + d0 + 8], proto[c * 256 + d0 + 9]);
        g_simB2[id] = make_uint2(h0, h1);
    } else {
        // z B: k = codebook c (contraction), n = d; chunked by (dc, kz)
        int e = id - 8192;
        int lane = e & 31, nt = (e >> 5) & 7, kz = (e >> 8) & 7, dc = (e >> 11) & 3;
        int d  = dc * 64 + nt * 8 + (lane >> 2);
        int c0 = kz * 16 + (lane & 3) * 2;
        uint32_t h0 = packh(proto[c0 * 256 + d],       proto[(c0 + 1) * 256 + d]);
        uint32_t h1 = packh(proto[(c0 + 8) * 256 + d], proto[(c0 + 9) * 256 + d]);
        g_zB2[e] = make_uint2(h0, h1);
    }
}

#define MMA4H(c, a0, a1, a2, a3, b0, b1)                                    \
    asm volatile("mma.sync.aligned.m16n8k16.row.col.f32.f16.f16.f32 "       \
        "{%0,%1,%2,%3}, {%4,%5,%6,%7}, {%8,%9}, {%0,%1,%2,%3};"             \
        : "+f"((c)[0]), "+f"((c)[1]), "+f"((c)[2]), "+f"((c)[3])            \
        : "r"(a0), "r"(a1), "r"(a2), "r"(a3), "r"(b0), "r"(b1))

__device__ __forceinline__ uint32_t smem_u32(const void* p) {
    uint32_t a;
    asm("{ .reg .u64 t; cvta.to.shared.u64 t, %1; cvt.u32.u64 %0, t; }" : "=r"(a) : "l"(p));
    return a;
}
__device__ __forceinline__ void cp16(uint32_t dst, const void* src) {
    asm volatile("cp.async.cg.shared.global [%0], [%1], 16;" :: "r"(dst), "l"(src) : "memory");
}
__device__ __forceinline__ void cp8(uint32_t dst, const void* src) {
    asm volatile("cp.async.ca.shared.global [%0], [%1], 8;" :: "r"(dst), "l"(src) : "memory");
}
#define CP_COMMIT() asm volatile("cp.async.commit_group;" ::: "memory")
#define CP_WAIT(n)  asm volatile("cp.async.wait_group %0;" :: "n"(n) : "memory")

__global__ __launch_bounds__(NTHR, 2) void softcodebook_mma_kernel(
    const float* __restrict__ h, float* __restrict__ out)
{
    __shared__ uint2 sbuf[2048];   // 16KB ring (sim: 4x4KB, z: 8x2KB)
    const uint32_t sb = smem_u32(sbuf);
    const int tid = threadIdx.x;
    const int w = tid >> 5, lid = tid & 31;     // 8 warps
    const int g = lid >> 2, t4 = lid & 3;
    const int row0 = blockIdx.x * BR;

    // ---- prologue: async-stage sim chunks 0,1 (4KB each) ----
    cp16(sb + 0u * 4096u + (uint32_t)tid * 16u, g_simB2 + 0 * 512 + tid * 2);
    CP_COMMIT();
    cp16(sb + 1u * 4096u + (uint32_t)tid * 16u, g_simB2 + 1 * 512 + tid * 2);
    CP_COMMIT();

    // ---- warp-private row norms (batched 4 rows for MLP) ----
    float myrinv = 0.0f;
    #pragma unroll 1
    for (int b = 0; b < 4; ++b) {
        float4 va[4], vb[4];
        #pragma unroll
        for (int j = 0; j < 4; ++j) {
            const float4* hp = (const float4*)(h + (size_t)(row0 + w * 16 + b * 4 + j) * 256);
            va[j] = hp[lid]; vb[j] = hp[lid + 32];
        }
        #pragma unroll
        for (int j = 0; j < 4; ++j) {
            float ss = va[j].x*va[j].x + va[j].y*va[j].y + va[j].z*va[j].z + va[j].w*va[j].w
                     + vb[j].x*vb[j].x + vb[j].y*vb[j].y + vb[j].z*vb[j].z + vb[j].w*vb[j].w;
            #pragma unroll
            for (int o = 16; o >= 1; o >>= 1) ss += __shfl_xor_sync(0xffffffffu, ss, o);
            if (lid == b * 4 + j) myrinv = 1.0f / fmaxf(sqrtf(ss), 1e-12f);
        }
    }
    const float s0r = __shfl_sync(0xffffffffu, myrinv, g);
    const float s1r = __shfl_sync(0xffffffffu, myrinv, g + 8);

    // sim accumulators: C[nt][4] -> rows (g, g+8), cols nt*8 + t4*2 (+1)
    float C[16][4];
    #pragma unroll
    for (int nt = 0; nt < 16; ++nt)
        #pragma unroll
        for (int j = 0; j < 4; ++j) C[nt][j] = 0.0f;

    // ---- sim GEMM: 16 k-chunks, fp16 2-pass (hi*hi + lo*hi) ----
    const size_t rA = (size_t)(row0 + w * 16 + g) * 256;
    const size_t rB = rA + 8 * 256;
    float2 v0, v1, v2, v3;
    {
        int db = t4 * 2;
        v0 = *(const float2*)(h + rA + db);
        v1 = *(const float2*)(h + rB + db);
        v2 = *(const float2*)(h + rA + db + 8);
        v3 = *(const float2*)(h + rB + db + 8);
    }
    #pragma unroll 1
    for (int kc = 0; kc < 16; ++kc) {
        if (kc + 2 < 16) {
            int c = kc + 2, bi = c & 3;
            cp16(sb + (uint32_t)bi * 4096u + (uint32_t)tid * 16u, g_simB2 + c * 512 + tid * 2);
            CP_COMMIT();
            CP_WAIT(2);
        } else if (kc + 1 < 16) {
            CP_WAIT(1);
        } else {
            CP_WAIT(0);
        }
        __syncthreads();

        float2 n0, n1, n2, n3;
        if (kc < 15) {
            int db = (kc + 1) * 16 + t4 * 2;
            n0 = *(const float2*)(h + rA + db);
            n1 = *(const float2*)(h + rB + db);
            n2 = *(const float2*)(h + rA + db + 8);
            n3 = *(const float2*)(h + rB + db + 8);
        }
        uint32_t a0, a1, a2, a3, l0, l1, l2, l3;
        split2h(v0.x * s0r, v0.y * s0r, a0, l0);
        split2h(v1.x * s1r, v1.y * s1r, a1, l1);
        split2h(v2.x * s0r, v2.y * s0r, a2, l2);
        split2h(v3.x * s1r, v3.y * s1r, a3, l3);
        const uint2* Bp = sbuf + (kc & 3) * 512 + lid;
        #pragma unroll
        for (int q = 0; q < 4; ++q) {
            uint2 b0 = Bp[(q * 4 + 0) * 32];
            uint2 b1 = Bp[(q * 4 + 1) * 32];
            uint2 b2 = Bp[(q * 4 + 2) * 32];
            uint2 b3 = Bp[(q * 4 + 3) * 32];
            MMA4H(C[q*4+0], a0, a1, a2, a3, b0.x, b0.y);
            MMA4H(C[q*4+1], a0, a1, a2, a3, b1.x, b1.y);
            MMA4H(C[q*4+2], a0, a1, a2, a3, b2.x, b2.y);
            MMA4H(C[q*4+3], a0, a1, a2, a3, b3.x, b3.y);
            MMA4H(C[q*4+0], l0, l1, l2, l3, b0.x, b0.y);
            MMA4H(C[q*4+1], l0, l1, l2, l3, b1.x, b1.y);
            MMA4H(C[q*4+2], l0, l1, l2, l3, b2.x, b2.y);
            MMA4H(C[q*4+3], l0, l1, l2, l3, b3.x, b3.y);
        }
        v0 = n0; v1 = n1; v2 = n2; v3 = n3;
    }

    // ---- softmax over K=128 (quad shfl), write p, split to PH/PL regs ----
    uint32_t PH[8][4], PL[8][4];
    {
        float mx0 = -1e30f, mx1 = -1e30f;
        #pragma unroll
        for (int nt = 0; nt < 16; ++nt) {
            mx0 = fmaxf(mx0, fmaxf(C[nt][0], C[nt][1]));
            mx1 = fmaxf(mx1, fmaxf(C[nt][2], C[nt][3]));
        }
        mx0 = fmaxf(mx0, __shfl_xor_sync(0xffffffffu, mx0, 1));
        mx0 = fmaxf(mx0, __shfl_xor_sync(0xffffffffu, mx0, 2));
        mx1 = fmaxf(mx1, __shfl_xor_sync(0xffffffffu, mx1, 1));
        mx1 = fmaxf(mx1, __shfl_xor_sync(0xffffffffu, mx1, 2));
        float s0 = 0.0f, s1 = 0.0f;
        #pragma unroll
        for (int nt = 0; nt < 16; ++nt) {
            C[nt][0] = __expf((C[nt][0] - mx0) * 10.0f); s0 += C[nt][0];
            C[nt][1] = __expf((C[nt][1] - mx0) * 10.0f); s0 += C[nt][1];
            C[nt][2] = __expf((C[nt][2] - mx1) * 10.0f); s1 += C[nt][2];
            C[nt][3] = __expf((C[nt][3] - mx1) * 10.0f); s1 += C[nt][3];
        }
        s0 += __shfl_xor_sync(0xffffffffu, s0, 1);
        s0 += __shfl_xor_sync(0xffffffffu, s0, 2);
        s1 += __shfl_xor_sync(0xffffffffu, s1, 1);
        s1 += __shfl_xor_sync(0xffffffffu, s1, 2);
        float i0 = 1.0f / s0, i1 = 1.0f / s1;
        size_t prow0 = (size_t)(row0 + w * 16 + g) * 128 + t4 * 2;
        size_t prow1 = prow0 + 8 * 128;
        #pragma unroll
        for (int nt = 0; nt < 16; ++nt) {
            C[nt][0] *= i0; C[nt][1] *= i0;
            C[nt][2] *= i1; C[nt][3] *= i1;
            *(float2*)(out + prow0 + nt * 8) = make_float2(C[nt][0], C[nt][1]);
            *(float2*)(out + prow1 + nt * 8) = make_float2(C[nt][2], C[nt][3]);
        }
        #pragma unroll
        for (int kz = 0; kz < 8; ++kz) {
            split2h(C[2 * kz][0],     C[2 * kz][1],     PH[kz][0], PL[kz][0]);
            split2h(C[2 * kz][2],     C[2 * kz][3],     PH[kz][1], PL[kz][1]);
            split2h(C[2 * kz + 1][0], C[2 * kz + 1][1], PH[kz][2], PL[kz][2]);
            split2h(C[2 * kz + 1][2], C[2 * kz + 1][3], PH[kz][3], PL[kz][3]);
        }
    }

    // ---- z prologue: stage z chunks 0..3 (2KB each, ring of 8) ----
    #pragma unroll
    for (int zc = 0; zc < 4; ++zc) {
        cp8(sb + (uint32_t)zc * 2048u + (uint32_t)tid * 8u, g_zB2 + zc * 256 + tid);
        CP_COMMIT();
    }

    // ---- z GEMM: A = p (PH/PL regs), B streamed, fp16 2-pass ----
    float* zout = out + (size_t)RT_TOT * 128;
    #pragma unroll 1
    for (int dc = 0; dc < 4; ++dc) {
        float Z[8][4];
        #pragma unroll
        for (int nt = 0; nt < 8; ++nt)
            #pragma unroll
            for (int j = 0; j < 4; ++j) Z[nt][j] = 0.0f;

        #pragma unroll 1
        for (int kz = 0; kz < 8; ++kz) {
            int zc = dc * 8 + kz;
            if (zc + 4 < 32) {
                int c = zc + 4;
                cp8(sb + (uint32_t)(c & 7) * 2048u + (uint32_t)tid * 8u, g_zB2 + c * 256 + tid);
                CP_COMMIT();
                CP_WAIT(4);
            } else {
                int rem = 31 - zc;
                if (rem == 3)      { CP_WAIT(3); }
                else if (rem == 2) { CP_WAIT(2); }
                else if (rem == 1) { CP_WAIT(1); }
                else               { CP_WAIT(0); }
            }
            __syncthreads();

            const uint2* Bp = sbuf + (zc & 7) * 256 + lid;
            #pragma unroll
            for (int q = 0; q < 2; ++q) {
                uint2 b0 = Bp[(q * 4 + 0) * 32];
                uint2 b1 = Bp[(q * 4 + 1) * 32];
                uint2 b2 = Bp[(q * 4 + 2) * 32];
                uint2 b3 = Bp[(q * 4 + 3) * 32];
                MMA4H(Z[q*4+0], PH[kz][0], PH[kz][1], PH[kz][2], PH[kz][3], b0.x, b0.y);
                MMA4H(Z[q*4+1], PH[kz][0], PH[kz][1], PH[kz][2], PH[kz][3], b1.x, b1.y);
                MMA4H(Z[q*4+2], PH[kz][0], PH[kz][1], PH[kz][2], PH[kz][3], b2.x, b2.y);
                MMA4H(Z[q*4+3], PH[kz][0], PH[kz][1], PH[kz][2], PH[kz][3], b3.x, b3.y);
                MMA4H(Z[q*4+0], PL[kz][0], PL[kz][1], PL[kz][2], PL[kz][3], b0.x, b0.y);
                MMA4H(Z[q*4+1], PL[kz][0], PL[kz][1], PL[kz][2], PL[kz][3], b1.x, b1.y);
                MMA4H(Z[q*4+2], PL[kz][0], PL[kz][1], PL[kz][2], PL[kz][3], b2.x, b2.y);
                MMA4H(Z[q*4+3], PL[kz][0], PL[kz][1], PL[kz][2], PL[kz][3], b3.x, b3.y);
            }
        }
        {
            size_t zr0 = (size_t)(row0 + w * 16 + g) * 256 + dc * 64 + t4 * 2;
            size_t zr1 = zr0 + 8 * 256;
            #pragma unroll
            for (int nt = 0; nt < 8; ++nt) {
                *(float2*)(zout + zr0 + nt * 8) = make_float2(Z[nt][0], Z[nt][1]);
                *(float2*)(zout + zr1 + nt * 8) = make_float2(Z[nt][2], Z[nt][3]);
            }
        }
    }
}

extern "C" void kernel_launch(void* const* d_in, const int* in_sizes, int n_in,
                              void* d_out, int out_size) {
    const float* h     = (const float*)d_in[0];   // (64,1024,256) fp32
    const float* proto = (const float*)d_in[1];   // (128,256) fp32
    float* out = (float*)d_out;                   // p (65536*128) ++ z (65536*256)

    prep_kernel<<<64, 256>>>(proto);
    softcodebook_mma_kernel<<<NGRID, NTHR>>>(h, out);
}